// round 11
// baseline (speedup 1.0000x reference)
#include <cuda_runtime.h>
#include <math.h>
#include <stdint.h>

#define NNODES_MAX 100000
#define EDGES_MAX  3200000
#define SCAN_BLK   1024
#define MAX_SBLOCKS 128
#define XIN_LD     68
#define WRND_MAX   160000
#define NCHUNK     4

// ---- static scratch ----
__device__ int   g_cnt[NNODES_MAX];
__device__ int   g_rowptr[NNODES_MAX + 1];
__device__ int   g_bsum[MAX_SBLOCKS];
__device__ float g_dinv[NNODES_MAX];
__device__ int2  g_edges[EDGES_MAX];
__device__ __align__(16) float g_xin[(size_t)NNODES_MAX * XIN_LD];
__device__ __align__(16) float g_hA[(size_t)NNODES_MAX * 256];
__device__ __align__(16) float g_hB[(size_t)NNODES_MAX * 256];
__device__ __align__(16) float g_hC[(size_t)NNODES_MAX * 256];
__device__ __align__(16) float g_wrnd[WRND_MAX];

__device__ __forceinline__ float gelu_f(float x) {
    float u = 0.7978845608028654f * (x + 0.044715f * x * x * x);
    return 0.5f * x * (1.0f + tanhf(u));
}

__device__ __forceinline__ float tf32r(float f) {
    uint32_t u;
    asm("cvt.rna.tf32.f32 %0, %1;" : "=r"(u) : "f"(f));
    return __uint_as_float(u);
}

__device__ __forceinline__ void mma_tf32(float* c, const uint32_t* a, const uint32_t* b) {
    asm volatile(
        "mma.sync.aligned.m16n8k8.row.col.f32.tf32.tf32.f32 "
        "{%0,%1,%2,%3}, {%4,%5,%6,%7}, {%8,%9}, {%0,%1,%2,%3};"
        : "+f"(c[0]), "+f"(c[1]), "+f"(c[2]), "+f"(c[3])
        : "r"(a[0]), "r"(a[1]), "r"(a[2]), "r"(a[3]), "r"(b[0]), "r"(b[1]));
}

__device__ __forceinline__ void cp_async16(uint32_t sdst, const void* gsrc, int src_bytes) {
    asm volatile("cp.async.cg.shared.global [%0], [%1], 16, %2;"
                 :: "r"(sdst), "l"(gsrc), "r"(src_bytes));
}
__device__ __forceinline__ void cp_commit() {
    asm volatile("cp.async.commit_group;");
}
template <int N>
__device__ __forceinline__ void cp_wait() {
    asm volatile("cp.async.wait_group %0;" :: "n"(N));
}

// ---------------- preprocessing ----------------

__global__ void zero_kernel(int n) {
    int i = blockIdx.x * blockDim.x + threadIdx.x;
    if (i < n) g_cnt[i] = 0;
}

__global__ void hist_kernel(const int* __restrict__ dst, int E) {
    int i = blockIdx.x * blockDim.x + threadIdx.x;
    int base = i * 4;
    if (base + 3 < E) {
        int4 d = *(const int4*)(dst + base);
        atomicAdd(&g_cnt[d.x], 1);
        atomicAdd(&g_cnt[d.y], 1);
        atomicAdd(&g_cnt[d.z], 1);
        atomicAdd(&g_cnt[d.w], 1);
    } else {
        for (int j = base; j < E; j++) atomicAdd(&g_cnt[dst[j]], 1);
    }
}

__global__ void scan1_kernel(int n) {
    __shared__ int ws[32];
    int tid = threadIdx.x, lane = tid & 31, wid = tid >> 5;
    int i = blockIdx.x * SCAN_BLK + tid;
    int v = (i < n) ? g_cnt[i] : 0;
    if (i < n) g_dinv[i] = rsqrtf((float)(v + 1));
    int x = v;
    #pragma unroll
    for (int off = 1; off < 32; off <<= 1) {
        int t = __shfl_up_sync(0xffffffffu, x, off);
        if (lane >= off) x += t;
    }
    if (lane == 31) ws[wid] = x;
    __syncthreads();
    if (wid == 0) {
        int w = ws[lane];
        #pragma unroll
        for (int off = 1; off < 32; off <<= 1) {
            int t = __shfl_up_sync(0xffffffffu, w, off);
            if (lane >= off) w += t;
        }
        ws[lane] = w;
    }
    __syncthreads();
    int woff = (wid > 0) ? ws[wid - 1] : 0;
    if (i < n) g_rowptr[i] = woff + x - v;
    if (tid == 0) g_bsum[blockIdx.x] = ws[31];
}

__global__ void scan2_kernel(int nb, int n) {
    __shared__ int s[MAX_SBLOCKS];
    int tid = threadIdx.x;
    if (tid < nb) s[tid] = g_bsum[tid];
    __syncthreads();
    if (tid == 0) {
        int run = 0;
        for (int i = 0; i < nb; i++) { int v = s[i]; s[i] = run; run += v; }
        g_rowptr[n] = run;
    }
    __syncthreads();
    if (tid < nb) g_bsum[tid] = s[tid];
}

__global__ void scan3_kernel(int n) {
    int i = blockIdx.x * SCAN_BLK + threadIdx.x;
    if (i < n) g_rowptr[i] += g_bsum[blockIdx.x];
}

__global__ void fill_kernel(const int* __restrict__ src,
                            const int* __restrict__ dst, int E) {
    int i = blockIdx.x * blockDim.x + threadIdx.x;
    if (i < E) {
        int s = src[i];
        int d = dst[i];
        int pos = g_rowptr[d] + atomicSub(&g_cnt[d], 1) - 1;
        g_edges[pos] = make_int2(s, __float_as_int(g_dinv[s] * g_dinv[d]));
    }
}

__global__ void concat_kernel(const float* __restrict__ x, const float* __restrict__ t, int n) {
    int gid = blockIdx.x * blockDim.x + threadIdx.x;
    int row = gid >> 4;
    int sub = gid & 15;
    if (row < n) {
        float4 v = *(const float4*)(x + (size_t)row * 64 + sub * 4);
        v.x = tf32r(v.x); v.y = tf32r(v.y); v.z = tf32r(v.z); v.w = tf32r(v.w);
        *(float4*)(g_xin + (size_t)row * XIN_LD + sub * 4) = v;
        if (sub == 0) g_xin[(size_t)row * XIN_LD + 64] = tf32r(t[row]);
    }
}

__global__ void roundw_kernel(const float* __restrict__ w, int off, int count) {
    int i = blockIdx.x * blockDim.x + threadIdx.x;
    if (i < count) g_wrnd[off + i] = tf32r(w[i]);
}

// ---------------- TF32 tensor-core GEMM, 3-stage cp.async pipeline ----------------
#define MBIAS 1
#define MGELU 2
#define MRND  4
#define AST 20
#define WST 72
#define STAGES 3
__global__ void gemm_tc_kernel(const float* __restrict__ A, const float* __restrict__ W,
                               const float* __restrict__ bias, float* __restrict__ C,
                               int M, int K, int N, int lda, int mode) {
    __shared__ float Asm[STAGES][128 * AST];
    __shared__ float Wsm[STAGES][16 * WST];

    int m0 = blockIdx.x * 128;
    int n0 = blockIdx.y * 64;
    int tid = threadIdx.x;
    int wid = tid >> 5;
    int lane = tid & 31;
    int g  = lane >> 2;
    int tg = lane & 3;
    int wm = (wid & 3) * 32;
    int wn = (wid >> 2) * 32;

    float acc[2][4][4];
    #pragma unroll
    for (int mt = 0; mt < 2; mt++)
        #pragma unroll
        for (int nt = 0; nt < 4; nt++)
            #pragma unroll
            for (int q = 0; q < 4; q++) acc[mt][nt][q] = 0.0f;

    int ar0 = tid >> 2;
    int asg = (tid & 3) * 4;
    int wr  = tid >> 4;
    int wsg = (tid & 15) * 4;

    int nkc = (K + 15) / 16;

    #pragma unroll
    for (int s = 0; s < STAGES - 1; s++) {
        if (s < nkc) {
            int kc = s * 16;
            #pragma unroll
            for (int j = 0; j < 2; j++) {
                int r = ar0 + 64 * j;
                int gk = kc + asg;
                int bytes = ((m0 + r) < M) ? max(0, min(16, (K - gk) * 4)) : 0;
                const float* src = A + (size_t)min(m0 + r, M - 1) * lda + min(gk, K - 1);
                cp_async16((uint32_t)__cvta_generic_to_shared(&Asm[s][r * AST + asg]), src, bytes);
            }
            int gk = kc + wr;
            int bytes = (gk < K) ? 16 : 0;
            const float* wsrc = W + (size_t)min(gk, K - 1) * N + n0 + wsg;
            cp_async16((uint32_t)__cvta_generic_to_shared(&Wsm[s][wr * WST + wsg]), wsrc, bytes);
        }
        cp_commit();
    }

    for (int kci = 0; kci < nkc; kci++) {
        cp_wait<STAGES - 2>();
        __syncthreads();

        {
            int pf = kci + STAGES - 1;
            if (pf < nkc) {
                int pb = pf % STAGES;
                int kc = pf * 16;
                #pragma unroll
                for (int j = 0; j < 2; j++) {
                    int r = ar0 + 64 * j;
                    int gk = kc + asg;
                    int bytes = ((m0 + r) < M) ? max(0, min(16, (K - gk) * 4)) : 0;
                    const float* src = A + (size_t)min(m0 + r, M - 1) * lda + min(gk, K - 1);
                    cp_async16((uint32_t)__cvta_generic_to_shared(&Asm[pb][r * AST + asg]), src, bytes);
                }
                int gk = kc + wr;
                int bytes = (gk < K) ? 16 : 0;
                const float* wsrc = W + (size_t)min(gk, K - 1) * N + n0 + wsg;
                cp_async16((uint32_t)__cvta_generic_to_shared(&Wsm[pb][wr * WST + wsg]), wsrc, bytes);
            }
            cp_commit();
        }

        const float* As = Asm[kci % STAGES];
        const float* Ws = Wsm[kci % STAGES];
        #pragma unroll
        for (int s = 0; s < 2; s++) {
            int kb = s * 8;
            uint32_t afr[2][4], bfr[4][2];
            #pragma unroll
            for (int mt = 0; mt < 2; mt++) {
                int r = wm + mt * 16 + g;
                afr[mt][0] = __float_as_uint(As[r * AST + kb + tg]);
                afr[mt][1] = __float_as_uint(As[(r + 8) * AST + kb + tg]);
                afr[mt][2] = __float_as_uint(As[r * AST + kb + tg + 4]);
                afr[mt][3] = __float_as_uint(As[(r + 8) * AST + kb + tg + 4]);
            }
            #pragma unroll
            for (int nt = 0; nt < 4; nt++) {
                int nn = wn + nt * 8 + g;
                bfr[nt][0] = __float_as_uint(Ws[(kb + tg) * WST + nn]);
                bfr[nt][1] = __float_as_uint(Ws[(kb + tg + 4) * WST + nn]);
            }
            #pragma unroll
            for (int mt = 0; mt < 2; mt++)
                #pragma unroll
                for (int nt = 0; nt < 4; nt++)
                    mma_tf32(acc[mt][nt], afr[mt], bfr[nt]);
        }
    }

    #pragma unroll
    for (int mt = 0; mt < 2; mt++) {
        int r0 = m0 + wm + mt * 16 + g;
        int r1 = r0 + 8;
        #pragma unroll
        for (int nt = 0; nt < 4; nt++) {
            int cb = n0 + wn + nt * 8 + 2 * tg;
            float bl0 = 0.f, bl1 = 0.f;
            if (mode & MBIAS) { bl0 = bias[cb]; bl1 = bias[cb + 1]; }
            float v0 = acc[mt][nt][0] + bl0;
            float v1 = acc[mt][nt][1] + bl1;
            float v2 = acc[mt][nt][2] + bl0;
            float v3 = acc[mt][nt][3] + bl1;
            if (mode & MGELU) { v0 = gelu_f(v0); v1 = gelu_f(v1); v2 = gelu_f(v2); v3 = gelu_f(v3); }
            if (mode & MRND)  { v0 = tf32r(v0); v1 = tf32r(v1); v2 = tf32r(v2); v3 = tf32r(v3); }
            if (r0 < M) { C[(size_t)r0 * N + cb] = v0; C[(size_t)r0 * N + cb + 1] = v1; }
            if (r1 < M) { C[(size_t)r1 * N + cb] = v2; C[(size_t)r1 * N + cb + 1] = v3; }
        }
    }
}

// ---------------- aggregation (warp per node, node-range chunked) ----------------
template <int VW, bool EPI, bool RND>
__global__ void agg_kernel(const float* __restrict__ h, const float* __restrict__ bias,
                           float* __restrict__ out, int nd0, int nd1) {
    int warp = nd0 + ((blockIdx.x * blockDim.x + threadIdx.x) >> 5);
    int lane = threadIdx.x & 31;
    if (warp >= nd1) return;
    const int d = 32 * VW;
    const int col = lane * VW;

    float acc[VW];
    #pragma unroll
    for (int r = 0; r < VW; r++) acc[r] = 0.0f;

    int beg = g_rowptr[warp];
    int end = g_rowptr[warp + 1];
    for (int base = beg; base < end; base += 32) {
        int2 ed = make_int2(0, 0);
        if (base + lane < end) ed = g_edges[base + lane];
        int cnt = min(32, end - base);
        for (int j = 0; j < cnt; j++) {
            int s   = __shfl_sync(0xffffffffu, ed.x, j);
            float w = __int_as_float(__shfl_sync(0xffffffffu, ed.y, j));
            const float* hr = h + (size_t)s * d + col;
            if (VW == 4) {
                float4 v = *(const float4*)hr;
                acc[0] = fmaf(w, v.x, acc[0]);
                acc[1] = fmaf(w, v.y, acc[1]);
                acc[2] = fmaf(w, v.z, acc[2]);
                acc[3] = fmaf(w, v.w, acc[3]);
            } else {
                float2 v = *(const float2*)hr;
                acc[0] = fmaf(w, v.x, acc[0]);
                acc[1] = fmaf(w, v.y, acc[1]);
            }
        }
    }
    float di = g_dinv[warp];
    float ws = di * di;
    const float* hs = h + (size_t)warp * d + col;
    if (VW == 4) {
        float4 v = *(const float4*)hs;
        acc[0] = fmaf(ws, v.x, acc[0]);
        acc[1] = fmaf(ws, v.y, acc[1]);
        acc[2] = fmaf(ws, v.z, acc[2]);
        acc[3] = fmaf(ws, v.w, acc[3]);
    } else {
        float2 v = *(const float2*)hs;
        acc[0] = fmaf(ws, v.x, acc[0]);
        acc[1] = fmaf(ws, v.y, acc[1]);
    }

    float* op = out + (size_t)warp * d + col;
    #pragma unroll
    for (int r = 0; r < VW; r++) {
        float v = acc[r];
        if (EPI) v = gelu_f(v + bias[col + r]);
        if (RND) v = tf32r(v);
        acc[r] = v;
    }
    if (VW == 4) *(float4*)op = make_float4(acc[0], acc[1], acc[2], acc[3]);
    else         *(float2*)op = make_float2(acc[0], acc[1]);
}

// ---------------- launch helpers ----------------

static inline void launch_gemm(cudaStream_t st, const float* A, const float* W,
                               const float* bias, float* C,
                               int M, int K, int N, int lda, int mode) {
    dim3 grid((M + 127) / 128, N / 64);
    gemm_tc_kernel<<<grid, 256, 0, st>>>(A, W, bias, C, M, K, N, lda, mode);
}

extern "C" void kernel_launch(void* const* d_in, const int* in_sizes, int n_in,
                              void* d_out, int out_size) {
    const float* x  = (const float*)d_in[0];
    const float* t  = (const float*)d_in[1];
    const int*   ei = (const int*)d_in[2];
    const float* W1 = (const float*)d_in[3];  const float* b1 = (const float*)d_in[4];
    const float* W2 = (const float*)d_in[5];  const float* b2 = (const float*)d_in[6];
    const float* W3 = (const float*)d_in[7];  const float* b3 = (const float*)d_in[8];
    const float* W4 = (const float*)d_in[9];  const float* b4 = (const float*)d_in[10];
    const float* F1 = (const float*)d_in[11]; const float* c1 = (const float*)d_in[12];
    const float* F2 = (const float*)d_in[13]; const float* c2 = (const float*)d_in[14];
    const float* F3 = (const float*)d_in[15]; const float* c3 = (const float*)d_in[16];
    float* out = (float*)d_out;

    int n = in_sizes[1];
    int E = in_sizes[2] / 2;
    if (n > NNODES_MAX) n = NNODES_MAX;
    if (E > EDGES_MAX)  E = EDGES_MAX;

    const int* src32 = ei;
    const int* dst32 = ei + E;

    float *hA, *hB, *hC, *xin, *wr;
    cudaGetSymbolAddress((void**)&hA,  g_hA);
    cudaGetSymbolAddress((void**)&hB,  g_hB);
    cudaGetSymbolAddress((void**)&hC,  g_hC);
    cudaGetSymbolAddress((void**)&xin, g_xin);
    cudaGetSymbolAddress((void**)&wr,  g_wrnd);

    static cudaStream_t s2 = nullptr;
    static cudaEvent_t ev[10];
    if (s2 == nullptr) {
        cudaStreamCreateWithFlags(&s2, cudaStreamNonBlocking);
        for (int i = 0; i < 10; i++) cudaEventCreateWithFlags(&ev[i], cudaEventDisableTiming);
    }
    cudaStream_t s0 = 0;
    cudaStream_t S[2] = { s0, s2 };

    int nb  = (n + 255) / 256;
    int eb4 = (E / 4 + 256) / 256;
    int eb  = (E + 255) / 256;
    int nsb = (n + SCAN_BLK - 1) / SCAN_BLK;

    // chunk bounds (multiples of 128)
    int q = ((n / NCHUNK + 127) / 128) * 128;
    int cb[NCHUNK + 1];
    for (int c = 0; c <= NCHUNK; c++) cb[c] = min(n, c * q);

    // ---- fork: CSR preprocessing on s2 ----
    cudaEventRecord(ev[0], s0);
    cudaStreamWaitEvent(s2, ev[0], 0);
    zero_kernel<<<nb, 256, 0, s2>>>(n);
    hist_kernel<<<eb4, 256, 0, s2>>>(dst32, E);
    scan1_kernel<<<nsb, SCAN_BLK, 0, s2>>>(n);
    scan2_kernel<<<1, 128, 0, s2>>>(nsb, n);
    scan3_kernel<<<nsb, SCAN_BLK, 0, s2>>>(n);
    fill_kernel<<<eb, 256, 0, s2>>>(src32, dst32, E);
    cudaEventRecord(ev[1], s2);               // CSR done

    // ---- S1 on s0: weights + concat + GEMM1 (xin -> hA) ----
    const int oW1 = 0,      nW1 = 65 * 64;
    const int oW2 = 4160,   nW2 = 64 * 128;
    const int oW3 = 12352,  nW3 = 128 * 256;
    const int oW4 = 45120,  nW4 = 256 * 128;
    const int oF1 = 77888,  nF1 = 128 * 256;
    const int oF2 = 110656, nF2 = 256 * 128;
    const int oF3 = 143424, nF3 = 128 * 64;
    roundw_kernel<<<(nW1 + 255) / 256, 256, 0, s0>>>(W1, oW1, nW1);
    roundw_kernel<<<(nW2 + 255) / 256, 256, 0, s0>>>(W2, oW2, nW2);
    roundw_kernel<<<(nW3 + 255) / 256, 256, 0, s0>>>(W3, oW3, nW3);
    roundw_kernel<<<(nW4 + 255) / 256, 256, 0, s0>>>(W4, oW4, nW4);
    roundw_kernel<<<(nF1 + 255) / 256, 256, 0, s0>>>(F1, oF1, nF1);
    roundw_kernel<<<(nF2 + 255) / 256, 256, 0, s0>>>(F2, oF2, nF2);
    roundw_kernel<<<(nF3 + 255) / 256, 256, 0, s0>>>(F3, oF3, nF3);
    concat_kernel<<<(n * 16 + 255) / 256, 256, 0, s0>>>(x, t, n);
    launch_gemm(s0, xin, wr + oW1, nullptr, hA, n, 65, 64, XIN_LD, 0);

    // ---- S2 on s0: aggL1 (gather hA -> hB), needs CSR ----
    cudaStreamWaitEvent(s0, ev[1], 0);
    {
        int blocks = (n * 32 + 255) / 256;
        agg_kernel<2, true, false><<<blocks, 256, 0, s0>>>(hA, b1, hB, 0, n);
    }
    cudaEventRecord(ev[2], s0);               // aggL1 done
    cudaStreamWaitEvent(s2, ev[2], 0);

    // ---- S3: per-chunk aggL2 (hB gather -> hA) -> gemmL2 (hA -> hC) ----
    for (int c = 0; c < NCHUNK; c++) {
        cudaStream_t st = S[c & 1];
        int r0 = cb[c], rows = cb[c + 1] - cb[c];
        if (rows <= 0) continue;
        int blocks = (rows * 32 + 255) / 256;
        agg_kernel<2, false, true><<<blocks, 256, 0, st>>>(hB, nullptr, hA, r0, r0 + rows);
        launch_gemm(st, hA + (size_t)r0 * 64, wr + oW2, b2, hC + (size_t)r0 * 128,
                    rows, 64, 128, 64, MBIAS | MGELU);
    }
    cudaEventRecord(ev[3], s0);
    cudaEventRecord(ev[4], s2);
    cudaStreamWaitEvent(s0, ev[4], 0);
    cudaStreamWaitEvent(s2, ev[3], 0);

    // ---- S4: per-chunk aggL3 (hC gather -> hA) -> gemmL3 (hA -> hB) -> gemmL4 (hB -> hA) ----
    for (int c = 0; c < NCHUNK; c++) {
        cudaStream_t st = S[c & 1];
        int r0 = cb[c], rows = cb[c + 1] - cb[c];
        if (rows <= 0) continue;
        int blocks = (rows * 32 + 255) / 256;
        agg_kernel<4, false, true><<<blocks, 256, 0, st>>>(hC, nullptr, hA, r0, r0 + rows);
        launch_gemm(st, hA + (size_t)r0 * 128, wr + oW3, b3, hB + (size_t)r0 * 256,
                    rows, 128, 256, 128, MBIAS | MGELU | MRND);
        launch_gemm(st, hB + (size_t)r0 * 256, wr + oW4, nullptr, hA + (size_t)r0 * 128,
                    rows, 256, 128, 256, 0);
    }
    cudaEventRecord(ev[5], s0);
    cudaEventRecord(ev[6], s2);
    cudaStreamWaitEvent(s0, ev[6], 0);
    cudaStreamWaitEvent(s2, ev[5], 0);

    // ---- S5: per-chunk aggL4 (hA gather -> hB) -> F1 (hB -> hC) -> F2 (hC -> hB) -> F3 (hB -> out) ----
    for (int c = 0; c < NCHUNK; c++) {
        cudaStream_t st = S[c & 1];
        int r0 = cb[c], rows = cb[c + 1] - cb[c];
        if (rows <= 0) continue;
        int blocks = (rows * 32 + 255) / 256;
        agg_kernel<4, true, true><<<blocks, 256, 0, st>>>(hA, b4, hB, r0, r0 + rows);
        launch_gemm(st, hB + (size_t)r0 * 128, wr + oF1, c1, hC + (size_t)r0 * 256,
                    rows, 128, 256, 128, MBIAS | MGELU | MRND);
        launch_gemm(st, hC + (size_t)r0 * 256, wr + oF2, c2, hB + (size_t)r0 * 128,
                    rows, 256, 128, 256, MBIAS | MGELU | MRND);
        launch_gemm(st, hB + (size_t)r0 * 128, wr + oF3, c3, out + (size_t)r0 * 64,
                    rows, 128, 64, 128, MBIAS);
    }
    // final join back to s0
    cudaEventRecord(ev[7], s2);
    cudaStreamWaitEvent(s0, ev[7], 0);
}

// round 14
// speedup vs baseline: 1.0501x; 1.0501x over previous
#include <cuda_runtime.h>
#include <math.h>
#include <stdint.h>

#define NNODES_MAX 100000
#define EDGES_MAX  3200000
#define SCAN_BLK   1024
#define MAX_SBLOCKS 128
#define XIN_LD     68
#define WRND_MAX   160000

// ---- static scratch ----
__device__ int   g_cnt[NNODES_MAX];
__device__ int   g_rowptr[NNODES_MAX + 1];
__device__ int   g_bsum[MAX_SBLOCKS];
__device__ float g_dinv[NNODES_MAX];
__device__ int2  g_edges[EDGES_MAX];
__device__ __align__(16) float g_xin[(size_t)NNODES_MAX * XIN_LD];
__device__ __align__(16) float g_hA[(size_t)NNODES_MAX * 256];
__device__ __align__(16) float g_hB[(size_t)NNODES_MAX * 256];
__device__ __align__(16) float g_wrnd[WRND_MAX];

__device__ __forceinline__ float gelu_f(float x) {
    float u = 0.7978845608028654f * (x + 0.044715f * x * x * x);
    return 0.5f * x * (1.0f + tanhf(u));
}

__device__ __forceinline__ float tf32r(float f) {
    uint32_t u;
    asm("cvt.rna.tf32.f32 %0, %1;" : "=r"(u) : "f"(f));
    return __uint_as_float(u);
}

__device__ __forceinline__ void mma_tf32(float* c, const uint32_t* a, const uint32_t* b) {
    asm volatile(
        "mma.sync.aligned.m16n8k8.row.col.f32.tf32.tf32.f32 "
        "{%0,%1,%2,%3}, {%4,%5,%6,%7}, {%8,%9}, {%0,%1,%2,%3};"
        : "+f"(c[0]), "+f"(c[1]), "+f"(c[2]), "+f"(c[3])
        : "r"(a[0]), "r"(a[1]), "r"(a[2]), "r"(a[3]), "r"(b[0]), "r"(b[1]));
}

__device__ __forceinline__ void cp_async16(uint32_t sdst, const void* gsrc, int src_bytes) {
    asm volatile("cp.async.cg.shared.global [%0], [%1], 16, %2;"
                 :: "r"(sdst), "l"(gsrc), "r"(src_bytes));
}
__device__ __forceinline__ void cp_commit() {
    asm volatile("cp.async.commit_group;");
}
template <int N>
__device__ __forceinline__ void cp_wait() {
    asm volatile("cp.async.wait_group %0;" :: "n"(N));
}

// ---------------- preprocessing ----------------

__global__ void zero_kernel(int n) {
    int i = blockIdx.x * blockDim.x + threadIdx.x;
    if (i < n) g_cnt[i] = 0;
}

__global__ void hist_kernel(const int* __restrict__ dst, int E) {
    int i = blockIdx.x * blockDim.x + threadIdx.x;
    int base = i * 4;
    if (base + 3 < E) {
        int4 d = *(const int4*)(dst + base);
        atomicAdd(&g_cnt[d.x], 1);
        atomicAdd(&g_cnt[d.y], 1);
        atomicAdd(&g_cnt[d.z], 1);
        atomicAdd(&g_cnt[d.w], 1);
    } else {
        for (int j = base; j < E; j++) atomicAdd(&g_cnt[dst[j]], 1);
    }
}

__global__ void scan1_kernel(int n) {
    __shared__ int ws[32];
    int tid = threadIdx.x, lane = tid & 31, wid = tid >> 5;
    int i = blockIdx.x * SCAN_BLK + tid;
    int v = (i < n) ? g_cnt[i] : 0;
    if (i < n) g_dinv[i] = rsqrtf((float)(v + 1));
    int x = v;
    #pragma unroll
    for (int off = 1; off < 32; off <<= 1) {
        int t = __shfl_up_sync(0xffffffffu, x, off);
        if (lane >= off) x += t;
    }
    if (lane == 31) ws[wid] = x;
    __syncthreads();
    if (wid == 0) {
        int w = ws[lane];
        #pragma unroll
        for (int off = 1; off < 32; off <<= 1) {
            int t = __shfl_up_sync(0xffffffffu, w, off);
            if (lane >= off) w += t;
        }
        ws[lane] = w;
    }
    __syncthreads();
    int woff = (wid > 0) ? ws[wid - 1] : 0;
    if (i < n) g_rowptr[i] = woff + x - v;
    if (tid == 0) g_bsum[blockIdx.x] = ws[31];
}

__global__ void scan2_kernel(int nb, int n) {
    __shared__ int s[MAX_SBLOCKS];
    int tid = threadIdx.x;
    if (tid < nb) s[tid] = g_bsum[tid];
    __syncthreads();
    if (tid == 0) {
        int run = 0;
        for (int i = 0; i < nb; i++) { int v = s[i]; s[i] = run; run += v; }
        g_rowptr[n] = run;
    }
    __syncthreads();
    if (tid < nb) g_bsum[tid] = s[tid];
}

__global__ void scan3_kernel(int n) {
    int i = blockIdx.x * SCAN_BLK + threadIdx.x;
    if (i < n) g_rowptr[i] += g_bsum[blockIdx.x];
}

__global__ void fill_kernel(const int* __restrict__ src,
                            const int* __restrict__ dst, int E) {
    int i = blockIdx.x * blockDim.x + threadIdx.x;
    if (i < E) {
        int s = src[i];
        int d = dst[i];
        int pos = g_rowptr[d] + atomicSub(&g_cnt[d], 1) - 1;
        g_edges[pos] = make_int2(s, __float_as_int(g_dinv[s] * g_dinv[d]));
    }
}

__global__ void concat_kernel(const float* __restrict__ x, const float* __restrict__ t, int n) {
    int gid = blockIdx.x * blockDim.x + threadIdx.x;
    int row = gid >> 4;
    int sub = gid & 15;
    if (row < n) {
        float4 v = *(const float4*)(x + (size_t)row * 64 + sub * 4);
        v.x = tf32r(v.x); v.y = tf32r(v.y); v.z = tf32r(v.z); v.w = tf32r(v.w);
        *(float4*)(g_xin + (size_t)row * XIN_LD + sub * 4) = v;
        if (sub == 0) g_xin[(size_t)row * XIN_LD + 64] = tf32r(t[row]);
    }
}

// all 7 weight matrices rounded in one launch
#define OW1 0
#define OW2 4160
#define OW3 12352
#define OW4 45120
#define OF1 77888
#define OF2 110656
#define OF3 143424
#define OWEND 151616
__global__ void roundw_all_kernel(const float* __restrict__ W1, const float* __restrict__ W2,
                                  const float* __restrict__ W3, const float* __restrict__ W4,
                                  const float* __restrict__ F1, const float* __restrict__ F2,
                                  const float* __restrict__ F3) {
    int i = blockIdx.x * blockDim.x + threadIdx.x;
    if (i >= OWEND) return;
    const float* src; int off;
    if      (i < OW2) { src = W1; off = OW1; }
    else if (i < OW3) { src = W2; off = OW2; }
    else if (i < OW4) { src = W3; off = OW3; }
    else if (i < OF1) { src = W4; off = OW4; }
    else if (i < OF2) { src = F1; off = OF1; }
    else if (i < OF3) { src = F2; off = OF2; }
    else              { src = F3; off = OF3; }
    g_wrnd[i] = tf32r(src[i - off]);
}

// ---------------- TF32 tensor-core GEMM, 3-stage cp.async, templated N-tile ----------------
// Block tile 128 x NT, 8 warps as 4(M) x 2(N), warp tile 32 x NT/2.
// DYNAMIC shared memory (static cap is 48KB; NT=128 needs 56.8KB).
#define MBIAS 1
#define MGELU 2
#define MRND  4
#define AST 20
#define STAGES 3
template <int NT>   // 64 or 128
__global__ void gemm_tc_kernel(const float* __restrict__ A, const float* __restrict__ W,
                               const float* __restrict__ bias, float* __restrict__ C,
                               int M, int K, int N, int lda, int mode) {
    const int WST = NT + 8;           // 72 / 136; both ≡8 mod 32 -> conflict-free frags
    const int NTN = NT / 16;          // n8 tiles per warp (4 or 8)
    const int ASZ = 128 * AST;        // floats per A stage
    const int WSZ = 16 * WST;         // floats per W stage
    extern __shared__ float smem[];
    float* Asm = smem;                   // [STAGES][ASZ]
    float* Wsm = smem + STAGES * ASZ;    // [STAGES][WSZ]

    int m0 = blockIdx.x * 128;
    int n0 = blockIdx.y * NT;
    int tid = threadIdx.x;
    int wid = tid >> 5;
    int lane = tid & 31;
    int g  = lane >> 2;
    int tg = lane & 3;
    int wm = (wid & 3) * 32;
    int wn = (wid >> 2) * (NT / 2);

    float acc[2][NTN][4];
    #pragma unroll
    for (int mt = 0; mt < 2; mt++)
        #pragma unroll
        for (int nt = 0; nt < NTN; nt++)
            #pragma unroll
            for (int q = 0; q < 4; q++) acc[mt][nt][q] = 0.0f;

    int ar0 = tid >> 2;
    int asg = (tid & 3) * 4;
    int wr  = tid >> 4;              // W k-row (0..15)
    int wc0 = (tid & 15) * 4;        // W first 16B segment (col in floats)

    int nkc = (K + 15) / 16;

    #pragma unroll
    for (int s = 0; s < STAGES - 1; s++) {
        if (s < nkc) {
            int kc = s * 16;
            #pragma unroll
            for (int j = 0; j < 2; j++) {
                int r = ar0 + 64 * j;
                int gk = kc + asg;
                int bytes = ((m0 + r) < M) ? max(0, min(16, (K - gk) * 4)) : 0;
                const float* src = A + (size_t)min(m0 + r, M - 1) * lda + min(gk, K - 1);
                cp_async16((uint32_t)__cvta_generic_to_shared(&Asm[s * ASZ + r * AST + asg]), src, bytes);
            }
            int gk = kc + wr;
            int bytes = (gk < K) ? 16 : 0;
            #pragma unroll
            for (int p = 0; p < NT / 64; p++) {
                int col = wc0 + p * 64;
                const float* wsrc = W + (size_t)min(gk, K - 1) * N + n0 + col;
                cp_async16((uint32_t)__cvta_generic_to_shared(&Wsm[s * WSZ + wr * WST + col]), wsrc, bytes);
            }
        }
        cp_commit();
    }

    for (int kci = 0; kci < nkc; kci++) {
        cp_wait<STAGES - 2>();
        __syncthreads();

        {
            int pf = kci + STAGES - 1;
            if (pf < nkc) {
                int pb = pf % STAGES;
                int kc = pf * 16;
                #pragma unroll
                for (int j = 0; j < 2; j++) {
                    int r = ar0 + 64 * j;
                    int gk = kc + asg;
                    int bytes = ((m0 + r) < M) ? max(0, min(16, (K - gk) * 4)) : 0;
                    const float* src = A + (size_t)min(m0 + r, M - 1) * lda + min(gk, K - 1);
                    cp_async16((uint32_t)__cvta_generic_to_shared(&Asm[pb * ASZ + r * AST + asg]), src, bytes);
                }
                int gk = kc + wr;
                int bytes = (gk < K) ? 16 : 0;
                #pragma unroll
                for (int p = 0; p < NT / 64; p++) {
                    int col = wc0 + p * 64;
                    const float* wsrc = W + (size_t)min(gk, K - 1) * N + n0 + col;
                    cp_async16((uint32_t)__cvta_generic_to_shared(&Wsm[pb * WSZ + wr * WST + col]), wsrc, bytes);
                }
            }
            cp_commit();
        }

        const float* As = Asm + (kci % STAGES) * ASZ;
        const float* Ws = Wsm + (kci % STAGES) * WSZ;
        #pragma unroll
        for (int s = 0; s < 2; s++) {
            int kb = s * 8;
            uint32_t afr[2][4], bfr[NTN][2];
            #pragma unroll
            for (int mt = 0; mt < 2; mt++) {
                int r = wm + mt * 16 + g;
                afr[mt][0] = __float_as_uint(As[r * AST + kb + tg]);
                afr[mt][1] = __float_as_uint(As[(r + 8) * AST + kb + tg]);
                afr[mt][2] = __float_as_uint(As[r * AST + kb + tg + 4]);
                afr[mt][3] = __float_as_uint(As[(r + 8) * AST + kb + tg + 4]);
            }
            #pragma unroll
            for (int nt = 0; nt < NTN; nt++) {
                int nn = wn + nt * 8 + g;
                bfr[nt][0] = __float_as_uint(Ws[(kb + tg) * WST + nn]);
                bfr[nt][1] = __float_as_uint(Ws[(kb + tg + 4) * WST + nn]);
            }
            #pragma unroll
            for (int mt = 0; mt < 2; mt++)
                #pragma unroll
                for (int nt = 0; nt < NTN; nt++)
                    mma_tf32(acc[mt][nt], afr[mt], bfr[nt]);
        }
    }

    #pragma unroll
    for (int mt = 0; mt < 2; mt++) {
        int r0 = m0 + wm + mt * 16 + g;
        int r1 = r0 + 8;
        #pragma unroll
        for (int nt = 0; nt < NTN; nt++) {
            int cb = n0 + wn + nt * 8 + 2 * tg;
            float bl0 = 0.f, bl1 = 0.f;
            if (mode & MBIAS) { bl0 = bias[cb]; bl1 = bias[cb + 1]; }
            float v0 = acc[mt][nt][0] + bl0;
            float v1 = acc[mt][nt][1] + bl1;
            float v2 = acc[mt][nt][2] + bl0;
            float v3 = acc[mt][nt][3] + bl1;
            if (mode & MGELU) { v0 = gelu_f(v0); v1 = gelu_f(v1); v2 = gelu_f(v2); v3 = gelu_f(v3); }
            if (mode & MRND)  { v0 = tf32r(v0); v1 = tf32r(v1); v2 = tf32r(v2); v3 = tf32r(v3); }
            if (r0 < M) { C[(size_t)r0 * N + cb] = v0; C[(size_t)r0 * N + cb + 1] = v1; }
            if (r1 < M) { C[(size_t)r1 * N + cb] = v2; C[(size_t)r1 * N + cb + 1] = v3; }
        }
    }
}

// ---------------- aggregation (warp per node, vectorized gathers) ----------------
template <int VW, bool EPI, bool RND>
__global__ void agg_kernel(const float* __restrict__ h, const float* __restrict__ bias,
                           float* __restrict__ out, int n) {
    int warp = (blockIdx.x * blockDim.x + threadIdx.x) >> 5;
    int lane = threadIdx.x & 31;
    if (warp >= n) return;
    const int d = 32 * VW;
    const int col = lane * VW;

    float acc[VW];
    #pragma unroll
    for (int r = 0; r < VW; r++) acc[r] = 0.0f;

    int beg = g_rowptr[warp];
    int end = g_rowptr[warp + 1];
    for (int base = beg; base < end; base += 32) {
        int2 ed = make_int2(0, 0);
        if (base + lane < end) ed = g_edges[base + lane];
        int cnt = min(32, end - base);
        for (int j = 0; j < cnt; j++) {
            int s   = __shfl_sync(0xffffffffu, ed.x, j);
            float w = __int_as_float(__shfl_sync(0xffffffffu, ed.y, j));
            const float* hr = h + (size_t)s * d + col;
            if (VW == 4) {
                float4 v = *(const float4*)hr;
                acc[0] = fmaf(w, v.x, acc[0]);
                acc[1] = fmaf(w, v.y, acc[1]);
                acc[2] = fmaf(w, v.z, acc[2]);
                acc[3] = fmaf(w, v.w, acc[3]);
            } else {
                float2 v = *(const float2*)hr;
                acc[0] = fmaf(w, v.x, acc[0]);
                acc[1] = fmaf(w, v.y, acc[1]);
            }
        }
    }
    float di = g_dinv[warp];
    float ws = di * di;
    const float* hs = h + (size_t)warp * d + col;
    if (VW == 4) {
        float4 v = *(const float4*)hs;
        acc[0] = fmaf(ws, v.x, acc[0]);
        acc[1] = fmaf(ws, v.y, acc[1]);
        acc[2] = fmaf(ws, v.z, acc[2]);
        acc[3] = fmaf(ws, v.w, acc[3]);
    } else {
        float2 v = *(const float2*)hs;
        acc[0] = fmaf(ws, v.x, acc[0]);
        acc[1] = fmaf(ws, v.y, acc[1]);
    }

    float* op = out + (size_t)warp * d + col;
    #pragma unroll
    for (int r = 0; r < VW; r++) {
        float v = acc[r];
        if (EPI) v = gelu_f(v + bias[col + r]);
        if (RND) v = tf32r(v);
        acc[r] = v;
    }
    if (VW == 4) *(float4*)op = make_float4(acc[0], acc[1], acc[2], acc[3]);
    else         *(float2*)op = make_float2(acc[0], acc[1]);
}

// ---------------- launch helpers ----------------

template <int NT>
static inline int gemm_smem_bytes() {
    return (STAGES * 128 * AST + STAGES * 16 * (NT + 8)) * 4;
}

template <int NT>
static inline void launch_gemm(cudaStream_t st, const float* A, const float* W,
                               const float* bias, float* C,
                               int M, int K, int N, int lda, int mode) {
    dim3 grid((M + 127) / 128, N / NT);
    gemm_tc_kernel<NT><<<grid, 256, gemm_smem_bytes<NT>(), st>>>(A, W, bias, C, M, K, N, lda, mode);
}

extern "C" void kernel_launch(void* const* d_in, const int* in_sizes, int n_in,
                              void* d_out, int out_size) {
    const float* x  = (const float*)d_in[0];
    const float* t  = (const float*)d_in[1];
    const int*   ei = (const int*)d_in[2];
    const float* W1 = (const float*)d_in[3];  const float* b1 = (const float*)d_in[4];
    const float* W2 = (const float*)d_in[5];  const float* b2 = (const float*)d_in[6];
    const float* W3 = (const float*)d_in[7];  const float* b3 = (const float*)d_in[8];
    const float* W4 = (const float*)d_in[9];  const float* b4 = (const float*)d_in[10];
    const float* F1 = (const float*)d_in[11]; const float* c1 = (const float*)d_in[12];
    const float* F2 = (const float*)d_in[13]; const float* c2 = (const float*)d_in[14];
    const float* F3 = (const float*)d_in[15]; const float* c3 = (const float*)d_in[16];
    float* out = (float*)d_out;

    int n = in_sizes[1];
    int E = in_sizes[2] / 2;
    if (n > NNODES_MAX) n = NNODES_MAX;
    if (E > EDGES_MAX)  E = EDGES_MAX;

    const int* src32 = ei;
    const int* dst32 = ei + E;

    float *hA, *hB, *xin, *wr;
    cudaGetSymbolAddress((void**)&hA,  g_hA);
    cudaGetSymbolAddress((void**)&hB,  g_hB);
    cudaGetSymbolAddress((void**)&xin, g_xin);
    cudaGetSymbolAddress((void**)&wr,  g_wrnd);

    static cudaStream_t s2 = nullptr;
    static cudaEvent_t evFork = nullptr, evJoin = nullptr;
    if (s2 == nullptr) {
        cudaStreamCreateWithFlags(&s2, cudaStreamNonBlocking);
        cudaEventCreateWithFlags(&evFork, cudaEventDisableTiming);
        cudaEventCreateWithFlags(&evJoin, cudaEventDisableTiming);
        // opt in to >48KB dynamic smem (one-time host attribute set)
        cudaFuncSetAttribute((const void*)gemm_tc_kernel<64>,
                             cudaFuncAttributeMaxDynamicSharedMemorySize, gemm_smem_bytes<64>());
        cudaFuncSetAttribute((const void*)gemm_tc_kernel<128>,
                             cudaFuncAttributeMaxDynamicSharedMemorySize, gemm_smem_bytes<128>());
    }
    cudaStream_t s0 = 0;

    int nb  = (n + 255) / 256;
    int eb4 = (E / 4 + 256) / 256;
    int eb  = (E + 255) / 256;
    int nsb = (n + SCAN_BLK - 1) / SCAN_BLK;

    // ---- fork: CSR preprocessing on s2 ----
    cudaEventRecord(evFork, s0);
    cudaStreamWaitEvent(s2, evFork, 0);
    zero_kernel<<<nb, 256, 0, s2>>>(n);
    hist_kernel<<<eb4, 256, 0, s2>>>(dst32, E);
    scan1_kernel<<<nsb, SCAN_BLK, 0, s2>>>(n);
    scan2_kernel<<<1, 128, 0, s2>>>(nsb, n);
    scan3_kernel<<<nsb, SCAN_BLK, 0, s2>>>(n);
    fill_kernel<<<eb, 256, 0, s2>>>(src32, dst32, E);
    cudaEventRecord(evJoin, s2);

    // ---- s0: weights + concat + GEMM1 ----
    roundw_all_kernel<<<(OWEND + 255) / 256, 256, 0, s0>>>(W1, W2, W3, W4, F1, F2, F3);
    concat_kernel<<<(n * 16 + 255) / 256, 256, 0, s0>>>(x, t, n);
    launch_gemm<64>(s0, xin, wr + OW1, nullptr, hA, n, 65, 64, XIN_LD, 0);

    // join: CSR ready before first aggregation
    cudaStreamWaitEvent(s0, evJoin, 0);

    int aggBlocks = (n * 32 + 255) / 256;

    // L1: agg_post(64) b1+gelu (feeds agg -> no round)
    agg_kernel<2, true, false><<<aggBlocks, 256, 0, s0>>>(hA, b1, hB, n);

    // L2: agg_pre(64) [round] -> GEMM2 b2+gelu (feeds agg -> no round)
    agg_kernel<2, false, true><<<aggBlocks, 256, 0, s0>>>(hB, nullptr, hA, n);
    launch_gemm<128>(s0, hA, wr + OW2, b2, hB, n, 64, 128, 64, MBIAS | MGELU);

    // L3: agg_pre(128) [round] -> GEMM3 b3+gelu [feeds GEMM4 -> round]
    agg_kernel<4, false, true><<<aggBlocks, 256, 0, s0>>>(hB, nullptr, hA, n);
    launch_gemm<128>(s0, hA, wr + OW3, b3, hB, n, 128, 256, 128, MBIAS | MGELU | MRND);

    // L4: GEMM4 (feeds agg -> no round) -> agg_post(128) b4+gelu [feeds F1 -> round]
    launch_gemm<128>(s0, hB, wr + OW4, nullptr, hA, n, 256, 128, 256, 0);
    agg_kernel<4, true, true><<<aggBlocks, 256, 0, s0>>>(hA, b4, hB, n);

    // MLP head
    launch_gemm<128>(s0, hB, wr + OF1, c1, hA, n, 128, 256, 128, MBIAS | MGELU | MRND);
    launch_gemm<128>(s0, hA, wr + OF2, c2, hB, n, 256, 128, 256, MBIAS | MGELU | MRND);
    launch_gemm<64>(s0, hB, wr + OF3, c3, out, n, 128, 64, 128, MBIAS);
}

// round 16
// speedup vs baseline: 1.1003x; 1.0478x over previous
#include <cuda_runtime.h>
#include <cuda_fp16.h>
#include <math.h>
#include <stdint.h>

#define NNODES_MAX 100000
#define EDGES_MAX  3200000
#define SCAN_BLK   1024
#define MAX_SBLOCKS 128
#define XIN_LD     68
#define WRND_MAX   160000

// ---- static scratch ----
__device__ int   g_cnt[NNODES_MAX];
__device__ int   g_rowptr[NNODES_MAX + 1];
__device__ int   g_bsum[MAX_SBLOCKS];
__device__ float g_dinv[NNODES_MAX];
__device__ int2  g_edges[EDGES_MAX];
__device__ __align__(16) float g_xin[(size_t)NNODES_MAX * XIN_LD];
__device__ __align__(16) float g_hA[(size_t)NNODES_MAX * 256];
__device__ __align__(16) float g_hB[(size_t)NNODES_MAX * 256];
__device__ __align__(16) float g_wrnd[WRND_MAX];

__device__ __forceinline__ float gelu_f(float x) {
    float u = 0.7978845608028654f * (x + 0.044715f * x * x * x);
    return 0.5f * x * (1.0f + tanhf(u));
}

__device__ __forceinline__ float tf32r(float f) {
    uint32_t u;
    asm("cvt.rna.tf32.f32 %0, %1;" : "=r"(u) : "f"(f));
    return __uint_as_float(u);
}

__device__ __forceinline__ void mma_tf32(float* c, const uint32_t* a, const uint32_t* b) {
    asm volatile(
        "mma.sync.aligned.m16n8k8.row.col.f32.tf32.tf32.f32 "
        "{%0,%1,%2,%3}, {%4,%5,%6,%7}, {%8,%9}, {%0,%1,%2,%3};"
        : "+f"(c[0]), "+f"(c[1]), "+f"(c[2]), "+f"(c[3])
        : "r"(a[0]), "r"(a[1]), "r"(a[2]), "r"(a[3]), "r"(b[0]), "r"(b[1]));
}

__device__ __forceinline__ void cp_async16(uint32_t sdst, const void* gsrc, int src_bytes) {
    asm volatile("cp.async.cg.shared.global [%0], [%1], 16, %2;"
                 :: "r"(sdst), "l"(gsrc), "r"(src_bytes));
}
__device__ __forceinline__ void cp_commit() {
    asm volatile("cp.async.commit_group;");
}
template <int N>
__device__ __forceinline__ void cp_wait() {
    asm volatile("cp.async.wait_group %0;" :: "n"(N));
}

// load 4 consecutive halves -> 4 floats (8B aligned)
__device__ __forceinline__ void ld_half4(const __half* p, float* f) {
    uint2 u = *(const uint2*)p;
    __half2 h01 = *reinterpret_cast<const __half2*>(&u.x);
    __half2 h23 = *reinterpret_cast<const __half2*>(&u.y);
    float2 a = __half22float2(h01);
    float2 b = __half22float2(h23);
    f[0] = a.x; f[1] = a.y; f[2] = b.x; f[3] = b.y;
}

// ---------------- preprocessing ----------------

__global__ void zero_kernel(int n) {
    int i = blockIdx.x * blockDim.x + threadIdx.x;
    if (i < n) g_cnt[i] = 0;
}

__global__ void hist_kernel(const int* __restrict__ dst, int E) {
    int i = blockIdx.x * blockDim.x + threadIdx.x;
    int base = i * 4;
    if (base + 3 < E) {
        int4 d = *(const int4*)(dst + base);
        atomicAdd(&g_cnt[d.x], 1);
        atomicAdd(&g_cnt[d.y], 1);
        atomicAdd(&g_cnt[d.z], 1);
        atomicAdd(&g_cnt[d.w], 1);
    } else {
        for (int j = base; j < E; j++) atomicAdd(&g_cnt[dst[j]], 1);
    }
}

__global__ void scan1_kernel(int n) {
    __shared__ int ws[32];
    int tid = threadIdx.x, lane = tid & 31, wid = tid >> 5;
    int i = blockIdx.x * SCAN_BLK + tid;
    int v = (i < n) ? g_cnt[i] : 0;
    if (i < n) g_dinv[i] = rsqrtf((float)(v + 1));
    int x = v;
    #pragma unroll
    for (int off = 1; off < 32; off <<= 1) {
        int t = __shfl_up_sync(0xffffffffu, x, off);
        if (lane >= off) x += t;
    }
    if (lane == 31) ws[wid] = x;
    __syncthreads();
    if (wid == 0) {
        int w = ws[lane];
        #pragma unroll
        for (int off = 1; off < 32; off <<= 1) {
            int t = __shfl_up_sync(0xffffffffu, w, off);
            if (lane >= off) w += t;
        }
        ws[lane] = w;
    }
    __syncthreads();
    int woff = (wid > 0) ? ws[wid - 1] : 0;
    if (i < n) g_rowptr[i] = woff + x - v;
    if (tid == 0) g_bsum[blockIdx.x] = ws[31];
}

__global__ void scan2_kernel(int nb, int n) {
    __shared__ int s[MAX_SBLOCKS];
    int tid = threadIdx.x;
    if (tid < nb) s[tid] = g_bsum[tid];
    __syncthreads();
    if (tid == 0) {
        int run = 0;
        for (int i = 0; i < nb; i++) { int v = s[i]; s[i] = run; run += v; }
        g_rowptr[n] = run;
    }
    __syncthreads();
    if (tid < nb) g_bsum[tid] = s[tid];
}

__global__ void scan3_kernel(int n) {
    int i = blockIdx.x * SCAN_BLK + threadIdx.x;
    if (i < n) g_rowptr[i] += g_bsum[blockIdx.x];
}

__global__ void fill_kernel(const int* __restrict__ src,
                            const int* __restrict__ dst, int E) {
    int i = blockIdx.x * blockDim.x + threadIdx.x;
    if (i < E) {
        int s = src[i];
        int d = dst[i];
        int pos = g_rowptr[d] + atomicSub(&g_cnt[d], 1) - 1;
        g_edges[pos] = make_int2(s, __float_as_int(g_dinv[s] * g_dinv[d]));
    }
}

__global__ void concat_kernel(const float* __restrict__ x, const float* __restrict__ t, int n) {
    int gid = blockIdx.x * blockDim.x + threadIdx.x;
    int row = gid >> 4;
    int sub = gid & 15;
    if (row < n) {
        float4 v = *(const float4*)(x + (size_t)row * 64 + sub * 4);
        v.x = tf32r(v.x); v.y = tf32r(v.y); v.z = tf32r(v.z); v.w = tf32r(v.w);
        *(float4*)(g_xin + (size_t)row * XIN_LD + sub * 4) = v;
        if (sub == 0) g_xin[(size_t)row * XIN_LD + 64] = tf32r(t[row]);
    }
}

// all 7 weight matrices rounded in one launch
#define OW1 0
#define OW2 4160
#define OW3 12352
#define OW4 45120
#define OF1 77888
#define OF2 110656
#define OF3 143424
#define OWEND 151616
__global__ void roundw_all_kernel(const float* __restrict__ W1, const float* __restrict__ W2,
                                  const float* __restrict__ W3, const float* __restrict__ W4,
                                  const float* __restrict__ F1, const float* __restrict__ F2,
                                  const float* __restrict__ F3) {
    int i = blockIdx.x * blockDim.x + threadIdx.x;
    if (i >= OWEND) return;
    const float* src; int off;
    if      (i < OW2) { src = W1; off = OW1; }
    else if (i < OW3) { src = W2; off = OW2; }
    else if (i < OW4) { src = W3; off = OW3; }
    else if (i < OF1) { src = W4; off = OW4; }
    else if (i < OF2) { src = F1; off = OF1; }
    else if (i < OF3) { src = F2; off = OF2; }
    else              { src = F3; off = OF3; }
    g_wrnd[i] = tf32r(src[i - off]);
}

// ---------------- TF32 tensor-core GEMM, 3-stage cp.async, templated N-tile ----------------
// Block tile 128 x NT, 8 warps as 4(M) x 2(N), warp tile 32 x NT/2. DYNAMIC smem.
#define MBIAS 1
#define MGELU 2
#define MRND  4
#define MHALF 8
#define AST 20
#define STAGES 3
template <int NT>   // 64 or 128
__global__ void gemm_tc_kernel(const float* __restrict__ A, const float* __restrict__ W,
                               const float* __restrict__ bias, float* __restrict__ C,
                               int M, int K, int N, int lda, int mode) {
    const int WST = NT + 8;           // 72 / 136; both ≡8 mod 32 -> conflict-free frags
    const int NTN = NT / 16;
    const int ASZ = 128 * AST;
    const int WSZ = 16 * WST;
    extern __shared__ float smem[];
    float* Asm = smem;
    float* Wsm = smem + STAGES * ASZ;

    int m0 = blockIdx.x * 128;
    int n0 = blockIdx.y * NT;
    int tid = threadIdx.x;
    int wid = tid >> 5;
    int lane = tid & 31;
    int g  = lane >> 2;
    int tg = lane & 3;
    int wm = (wid & 3) * 32;
    int wn = (wid >> 2) * (NT / 2);

    float acc[2][NTN][4];
    #pragma unroll
    for (int mt = 0; mt < 2; mt++)
        #pragma unroll
        for (int nt = 0; nt < NTN; nt++)
            #pragma unroll
            for (int q = 0; q < 4; q++) acc[mt][nt][q] = 0.0f;

    int ar0 = tid >> 2;
    int asg = (tid & 3) * 4;
    int wr  = tid >> 4;
    int wc0 = (tid & 15) * 4;

    int nkc = (K + 15) / 16;

    #pragma unroll
    for (int s = 0; s < STAGES - 1; s++) {
        if (s < nkc) {
            int kc = s * 16;
            #pragma unroll
            for (int j = 0; j < 2; j++) {
                int r = ar0 + 64 * j;
                int gk = kc + asg;
                int bytes = ((m0 + r) < M) ? max(0, min(16, (K - gk) * 4)) : 0;
                const float* src = A + (size_t)min(m0 + r, M - 1) * lda + min(gk, K - 1);
                cp_async16((uint32_t)__cvta_generic_to_shared(&Asm[s * ASZ + r * AST + asg]), src, bytes);
            }
            int gk = kc + wr;
            int bytes = (gk < K) ? 16 : 0;
            #pragma unroll
            for (int p = 0; p < NT / 64; p++) {
                int col = wc0 + p * 64;
                const float* wsrc = W + (size_t)min(gk, K - 1) * N + n0 + col;
                cp_async16((uint32_t)__cvta_generic_to_shared(&Wsm[s * WSZ + wr * WST + col]), wsrc, bytes);
            }
        }
        cp_commit();
    }

    for (int kci = 0; kci < nkc; kci++) {
        cp_wait<STAGES - 2>();
        __syncthreads();

        {
            int pf = kci + STAGES - 1;
            if (pf < nkc) {
                int pb = pf % STAGES;
                int kc = pf * 16;
                #pragma unroll
                for (int j = 0; j < 2; j++) {
                    int r = ar0 + 64 * j;
                    int gk = kc + asg;
                    int bytes = ((m0 + r) < M) ? max(0, min(16, (K - gk) * 4)) : 0;
                    const float* src = A + (size_t)min(m0 + r, M - 1) * lda + min(gk, K - 1);
                    cp_async16((uint32_t)__cvta_generic_to_shared(&Asm[pb * ASZ + r * AST + asg]), src, bytes);
                }
                int gk = kc + wr;
                int bytes = (gk < K) ? 16 : 0;
                #pragma unroll
                for (int p = 0; p < NT / 64; p++) {
                    int col = wc0 + p * 64;
                    const float* wsrc = W + (size_t)min(gk, K - 1) * N + n0 + col;
                    cp_async16((uint32_t)__cvta_generic_to_shared(&Wsm[pb * WSZ + wr * WST + col]), wsrc, bytes);
                }
            }
            cp_commit();
        }

        const float* As = Asm + (kci % STAGES) * ASZ;
        const float* Ws = Wsm + (kci % STAGES) * WSZ;
        #pragma unroll
        for (int s = 0; s < 2; s++) {
            int kb = s * 8;
            uint32_t afr[2][4], bfr[NTN][2];
            #pragma unroll
            for (int mt = 0; mt < 2; mt++) {
                int r = wm + mt * 16 + g;
                afr[mt][0] = __float_as_uint(As[r * AST + kb + tg]);
                afr[mt][1] = __float_as_uint(As[(r + 8) * AST + kb + tg]);
                afr[mt][2] = __float_as_uint(As[r * AST + kb + tg + 4]);
                afr[mt][3] = __float_as_uint(As[(r + 8) * AST + kb + tg + 4]);
            }
            #pragma unroll
            for (int nt = 0; nt < NTN; nt++) {
                int nn = wn + nt * 8 + g;
                bfr[nt][0] = __float_as_uint(Ws[(kb + tg) * WST + nn]);
                bfr[nt][1] = __float_as_uint(Ws[(kb + tg + 4) * WST + nn]);
            }
            #pragma unroll
            for (int mt = 0; mt < 2; mt++)
                #pragma unroll
                for (int nt = 0; nt < NTN; nt++)
                    mma_tf32(acc[mt][nt], afr[mt], bfr[nt]);
        }
    }

    __half* Ch = (__half*)C;
    #pragma unroll
    for (int mt = 0; mt < 2; mt++) {
        int r0 = m0 + wm + mt * 16 + g;
        int r1 = r0 + 8;
        #pragma unroll
        for (int nt = 0; nt < NTN; nt++) {
            int cb = n0 + wn + nt * 8 + 2 * tg;
            float bl0 = 0.f, bl1 = 0.f;
            if (mode & MBIAS) { bl0 = bias[cb]; bl1 = bias[cb + 1]; }
            float v0 = acc[mt][nt][0] + bl0;
            float v1 = acc[mt][nt][1] + bl1;
            float v2 = acc[mt][nt][2] + bl0;
            float v3 = acc[mt][nt][3] + bl1;
            if (mode & MGELU) { v0 = gelu_f(v0); v1 = gelu_f(v1); v2 = gelu_f(v2); v3 = gelu_f(v3); }
            if (mode & MRND)  { v0 = tf32r(v0); v1 = tf32r(v1); v2 = tf32r(v2); v3 = tf32r(v3); }
            if (mode & MHALF) {
                if (r0 < M) *(__half2*)&Ch[(size_t)r0 * N + cb] = __floats2half2_rn(v0, v1);
                if (r1 < M) *(__half2*)&Ch[(size_t)r1 * N + cb] = __floats2half2_rn(v2, v3);
            } else {
                if (r0 < M) { C[(size_t)r0 * N + cb] = v0; C[(size_t)r0 * N + cb + 1] = v1; }
                if (r1 < M) { C[(size_t)r1 * N + cb] = v2; C[(size_t)r1 * N + cb + 1] = v3; }
            }
        }
    }
}

// ---------------- aggregation (warp per node, vectorized gathers) ----------------
// HIN: gather source stored as fp16 (accumulate fp32). Output always fp32.
template <int VW, bool EPI, bool RND, bool HIN>
__global__ void agg_kernel(const float* __restrict__ h, const float* __restrict__ bias,
                           float* __restrict__ out, int n) {
    int warp = (blockIdx.x * blockDim.x + threadIdx.x) >> 5;
    int lane = threadIdx.x & 31;
    if (warp >= n) return;
    const int d = 32 * VW;
    const int col = lane * VW;
    const __half* hh = (const __half*)h;

    float acc[VW];
    #pragma unroll
    for (int r = 0; r < VW; r++) acc[r] = 0.0f;

    int beg = g_rowptr[warp];
    int end = g_rowptr[warp + 1];
    for (int base = beg; base < end; base += 32) {
        int2 ed = make_int2(0, 0);
        if (base + lane < end) ed = g_edges[base + lane];
        int cnt = min(32, end - base);
        for (int j = 0; j < cnt; j++) {
            int s   = __shfl_sync(0xffffffffu, ed.x, j);
            float w = __int_as_float(__shfl_sync(0xffffffffu, ed.y, j));
            if (HIN) {
                float f[4];
                ld_half4(hh + (size_t)s * d + col, f);   // VW==4 path
                acc[0] = fmaf(w, f[0], acc[0]);
                acc[1] = fmaf(w, f[1], acc[1]);
                acc[2] = fmaf(w, f[2], acc[2]);
                acc[3] = fmaf(w, f[3], acc[3]);
            } else if (VW == 4) {
                float4 v = *(const float4*)(h + (size_t)s * d + col);
                acc[0] = fmaf(w, v.x, acc[0]);
                acc[1] = fmaf(w, v.y, acc[1]);
                acc[2] = fmaf(w, v.z, acc[2]);
                acc[3] = fmaf(w, v.w, acc[3]);
            } else {
                float2 v = *(const float2*)(h + (size_t)s * d + col);
                acc[0] = fmaf(w, v.x, acc[0]);
                acc[1] = fmaf(w, v.y, acc[1]);
            }
        }
    }
    float di = g_dinv[warp];
    float ws = di * di;
    if (HIN) {
        float f[4];
        ld_half4(hh + (size_t)warp * d + col, f);
        #pragma unroll
        for (int r = 0; r < 4; r++) acc[r] = fmaf(ws, f[r], acc[r]);
    } else if (VW == 4) {
        float4 v = *(const float4*)(h + (size_t)warp * d + col);
        acc[0] = fmaf(ws, v.x, acc[0]);
        acc[1] = fmaf(ws, v.y, acc[1]);
        acc[2] = fmaf(ws, v.z, acc[2]);
        acc[3] = fmaf(ws, v.w, acc[3]);
    } else {
        float2 v = *(const float2*)(h + (size_t)warp * d + col);
        acc[0] = fmaf(ws, v.x, acc[0]);
        acc[1] = fmaf(ws, v.y, acc[1]);
    }

    float* op = out + (size_t)warp * d + col;
    #pragma unroll
    for (int r = 0; r < VW; r++) {
        float v = acc[r];
        if (EPI) v = gelu_f(v + bias[col + r]);
        if (RND) v = tf32r(v);
        acc[r] = v;
    }
    if (VW == 4) *(float4*)op = make_float4(acc[0], acc[1], acc[2], acc[3]);
    else         *(float2*)op = make_float2(acc[0], acc[1]);
}

// ---------------- launch helpers ----------------

template <int NT>
static inline int gemm_smem_bytes() {
    return (STAGES * 128 * AST + STAGES * 16 * (NT + 8)) * 4;
}

template <int NT>
static inline void launch_gemm(cudaStream_t st, const float* A, const float* W,
                               const float* bias, float* C,
                               int M, int K, int N, int lda, int mode) {
    dim3 grid((M + 127) / 128, N / NT);
    gemm_tc_kernel<NT><<<grid, 256, gemm_smem_bytes<NT>(), st>>>(A, W, bias, C, M, K, N, lda, mode);
}

extern "C" void kernel_launch(void* const* d_in, const int* in_sizes, int n_in,
                              void* d_out, int out_size) {
    const float* x  = (const float*)d_in[0];
    const float* t  = (const float*)d_in[1];
    const int*   ei = (const int*)d_in[2];
    const float* W1 = (const float*)d_in[3];  const float* b1 = (const float*)d_in[4];
    const float* W2 = (const float*)d_in[5];  const float* b2 = (const float*)d_in[6];
    const float* W3 = (const float*)d_in[7];  const float* b3 = (const float*)d_in[8];
    const float* W4 = (const float*)d_in[9];  const float* b4 = (const float*)d_in[10];
    const float* F1 = (const float*)d_in[11]; const float* c1 = (const float*)d_in[12];
    const float* F2 = (const float*)d_in[13]; const float* c2 = (const float*)d_in[14];
    const float* F3 = (const float*)d_in[15]; const float* c3 = (const float*)d_in[16];
    float* out = (float*)d_out;

    int n = in_sizes[1];
    int E = in_sizes[2] / 2;
    if (n > NNODES_MAX) n = NNODES_MAX;
    if (E > EDGES_MAX)  E = EDGES_MAX;

    const int* src32 = ei;
    const int* dst32 = ei + E;

    float *hA, *hB, *xin, *wr;
    cudaGetSymbolAddress((void**)&hA,  g_hA);
    cudaGetSymbolAddress((void**)&hB,  g_hB);
    cudaGetSymbolAddress((void**)&xin, g_xin);
    cudaGetSymbolAddress((void**)&wr,  g_wrnd);

    static cudaStream_t s2 = nullptr;
    static cudaEvent_t evFork = nullptr, evJoin = nullptr;
    if (s2 == nullptr) {
        cudaStreamCreateWithFlags(&s2, cudaStreamNonBlocking);
        cudaEventCreateWithFlags(&evFork, cudaEventDisableTiming);
        cudaEventCreateWithFlags(&evJoin, cudaEventDisableTiming);
        cudaFuncSetAttribute((const void*)gemm_tc_kernel<64>,
                             cudaFuncAttributeMaxDynamicSharedMemorySize, gemm_smem_bytes<64>());
        cudaFuncSetAttribute((const void*)gemm_tc_kernel<128>,
                             cudaFuncAttributeMaxDynamicSharedMemorySize, gemm_smem_bytes<128>());
    }
    cudaStream_t s0 = 0;

    int nb  = (n + 255) / 256;
    int eb4 = (E / 4 + 256) / 256;
    int eb  = (E + 255) / 256;
    int nsb = (n + SCAN_BLK - 1) / SCAN_BLK;

    // ---- fork: CSR preprocessing on s2 ----
    cudaEventRecord(evFork, s0);
    cudaStreamWaitEvent(s2, evFork, 0);
    zero_kernel<<<nb, 256, 0, s2>>>(n);
    hist_kernel<<<eb4, 256, 0, s2>>>(dst32, E);
    scan1_kernel<<<nsb, SCAN_BLK, 0, s2>>>(n);
    scan2_kernel<<<1, 128, 0, s2>>>(nsb, n);
    scan3_kernel<<<nsb, SCAN_BLK, 0, s2>>>(n);
    fill_kernel<<<eb, 256, 0, s2>>>(src32, dst32, E);
    cudaEventRecord(evJoin, s2);

    // ---- s0: weights + concat + GEMM1 ----
    roundw_all_kernel<<<(OWEND + 255) / 256, 256, 0, s0>>>(W1, W2, W3, W4, F1, F2, F3);
    concat_kernel<<<(n * 16 + 255) / 256, 256, 0, s0>>>(x, t, n);
    launch_gemm<64>(s0, xin, wr + OW1, nullptr, hA, n, 65, 64, XIN_LD, 0);

    // join: CSR ready before first aggregation
    cudaStreamWaitEvent(s0, evJoin, 0);

    int aggBlocks = (n * 32 + 255) / 256;

    // L1: agg_post(64) b1+gelu, fp32 (feeds agg -> no round)
    agg_kernel<2, true, false, false><<<aggBlocks, 256, 0, s0>>>(hA, b1, hB, n);

    // L2: agg_pre(64) [round] -> GEMM2 b2+gelu -> fp16 (feeds aggL3 gather)
    agg_kernel<2, false, true, false><<<aggBlocks, 256, 0, s0>>>(hB, nullptr, hA, n);
    launch_gemm<128>(s0, hA, wr + OW2, b2, hB, n, 64, 128, 64, MBIAS | MGELU | MHALF);

    // L3: agg_pre(128) fp16-in [round] -> GEMM3 b3+gelu [feeds GEMM4 -> round]
    agg_kernel<4, false, true, true><<<aggBlocks, 256, 0, s0>>>(hB, nullptr, hA, n);
    launch_gemm<128>(s0, hA, wr + OW3, b3, hB, n, 128, 256, 128, MBIAS | MGELU | MRND);

    // L4: GEMM4 -> fp16 (feeds aggL4 gather) -> agg_post(128) fp16-in b4+gelu [round]
    launch_gemm<128>(s0, hB, wr + OW4, nullptr, hA, n, 256, 128, 256, MHALF);
    agg_kernel<4, true, true, true><<<aggBlocks, 256, 0, s0>>>(hA, b4, hB, n);

    // MLP head (fp32 throughout)
    launch_gemm<128>(s0, hB, wr + OF1, c1, hA, n, 128, 256, 128, MBIAS | MGELU | MRND);
    launch_gemm<128>(s0, hA, wr + OF2, c2, hB, n, 256, 128, 256, MBIAS | MGELU | MRND);
    launch_gemm<64>(s0, hB, wr + OF3, c3, out, n, 128, 64, 128, MBIAS);
}